// round 1
// baseline (speedup 1.0000x reference)
#include <cuda_runtime.h>
#include <math.h>

#define B_  64
#define R_  32
#define H_  1024
#define IN_ 2048
#define M_  (B_*R_)   // 2048 rows for the embed GEMMs

// Scratch (allocation-free rule: __device__ globals)
__device__ __align__(16) float g_E[2][M_][H_];      // [0]=hist_embed, [1]=ques_embed
__device__ __align__(16) float g_att[B_][R_][R_];   // masked softmax weights

// ---------------------------------------------------------------------------
// Kernel A: fused dual GEMM (y & g branches share the X tile) + gated act.
//   E[m,n] = tanh(X@Wy + by) * leaky_relu(X@Wg + bg, 0.01)
// Tiles: BM=128, BN=64, BK=16; 256 threads; per-thread 8x4 micro-tile x2 mats.
// ---------------------------------------------------------------------------
#define BM 128
#define BN 64
#define BK 16

__global__ __launch_bounds__(256, 2)
void embed_kernel(const float* __restrict__ hist, const float* __restrict__ ques,
                  const float* __restrict__ Why, const float* __restrict__ bhy,
                  const float* __restrict__ Whg, const float* __restrict__ bhg,
                  const float* __restrict__ Wqy, const float* __restrict__ bqy,
                  const float* __restrict__ Wqg, const float* __restrict__ bqg)
{
    const int z = blockIdx.z;
    const float* X  = z ? ques : hist;
    const float* Wy = z ? Wqy : Why;
    const float* Wg = z ? Wqg : Whg;
    const float* by = z ? bqy : bhy;
    const float* bg = z ? bqg : bhg;
    float* E = &g_E[z][0][0];

    __shared__ __align__(16) float As [BK][BM + 4];  // k-major, padded
    __shared__ __align__(16) float Bys[BK][BN];
    __shared__ __align__(16) float Bgs[BK][BN];

    const int tid = threadIdx.x;
    const int tx = tid & 15;        // 0..15 -> n micro
    const int ty = tid >> 4;        // 0..15 -> m micro
    const int m0 = blockIdx.x * BM;
    const int n0 = blockIdx.y * BN;

    float accy[8][4], accg[8][4];
    #pragma unroll
    for (int i = 0; i < 8; i++)
        #pragma unroll
        for (int j = 0; j < 4; j++) { accy[i][j] = 0.f; accg[i][j] = 0.f; }

    for (int k0 = 0; k0 < IN_; k0 += BK) {
        // Load A tile 128x16 (512 float4), transpose to k-major in smem
        #pragma unroll
        for (int i = 0; i < 2; i++) {
            int idx = tid + i * 256;             // 0..511
            int row = idx >> 2;                  // 0..127
            int c4  = (idx & 3) << 2;            // 0,4,8,12
            float4 v = *(const float4*)(X + (size_t)(m0 + row) * IN_ + k0 + c4);
            As[c4 + 0][row] = v.x;
            As[c4 + 1][row] = v.y;
            As[c4 + 2][row] = v.z;
            As[c4 + 3][row] = v.w;
        }
        // Load both B tiles 16x64 (256 float4 each)
        {
            int row = tid >> 4;                  // 0..15
            int c   = (tid & 15) << 2;           // 0..60
            *(float4*)&Bys[row][c] = *(const float4*)(Wy + (size_t)(k0 + row) * H_ + n0 + c);
            *(float4*)&Bgs[row][c] = *(const float4*)(Wg + (size_t)(k0 + row) * H_ + n0 + c);
        }
        __syncthreads();

        #pragma unroll
        for (int kk = 0; kk < BK; kk++) {
            float a[8], bv[4], gv[4];
            *(float4*)&a[0] = *(float4*)&As[kk][ty * 8];
            *(float4*)&a[4] = *(float4*)&As[kk][ty * 8 + 4];
            *(float4*)bv    = *(float4*)&Bys[kk][tx << 2];
            *(float4*)gv    = *(float4*)&Bgs[kk][tx << 2];
            #pragma unroll
            for (int i = 0; i < 8; i++)
                #pragma unroll
                for (int j = 0; j < 4; j++) {
                    accy[i][j] += a[i] * bv[j];
                    accg[i][j] += a[i] * gv[j];
                }
        }
        __syncthreads();
    }

    // Epilogue: bias + tanh * leaky_relu, vectorized store
    #pragma unroll
    for (int i = 0; i < 8; i++) {
        int m = m0 + ty * 8 + i;
        float4 o;
        float* op = &o.x;
        #pragma unroll
        for (int j = 0; j < 4; j++) {
            int n = n0 + (tx << 2) + j;
            float yv = tanhf(accy[i][j] + by[n]);
            float gv = accg[i][j] + bg[n];
            gv = gv > 0.f ? gv : 0.01f * gv;
            op[j] = yv * gv;
        }
        *(float4*)&E[(size_t)m * H_ + n0 + (tx << 2)] = o;
    }
}

// ---------------------------------------------------------------------------
// Kernel B: per-batch scores + masked softmax.
//   score[q,h] = <Eq[q]*Eh[h], W_att> / max(||Eq[q]*Eh[h]||2, eps) + b_att
//   att*tril renormalized == softmax over h<=q.
// One block per batch, 256 threads, each thread a 2x2 (q,h) tile with
// {t, t+16} index pairing for conflict-free smem reads.
// ---------------------------------------------------------------------------
__global__ __launch_bounds__(256)
void score_kernel(const float* __restrict__ W_att, const float* __restrict__ b_att_p)
{
    const int b    = blockIdx.x;
    const int tid  = threadIdx.x;
    const int lane = tid & 31;
    const int warp = tid >> 5;

    __shared__ float sq[64][33];              // [k][q]
    __shared__ float sh[64][33];              // [k][h]
    __shared__ __align__(16) float sw[64];
    __shared__ float ss[32][33];              // scores

    const int q0 = tid >> 4;   // q pair {q0, q0+16}
    const int h0 = tid & 15;   // h pair {h0, h0+16}

    float s00 = 0.f, s01 = 0.f, s10 = 0.f, s11 = 0.f;
    float n00 = 0.f, n01 = 0.f, n10 = 0.f, n11 = 0.f;

    const float* Eq = &g_E[1][b * R_][0];
    const float* Eh = &g_E[0][b * R_][0];

    for (int k0 = 0; k0 < H_; k0 += 64) {
        #pragma unroll
        for (int i = 0; i < 2; i++) {
            int idx = tid + i * 256;         // 0..511 : 32 rows x 16 float4
            int r   = idx >> 4;              // 0..31
            int c4  = (idx & 15) << 2;       // 0..60
            float4 vq = *(const float4*)(Eq + (size_t)r * H_ + k0 + c4);
            sq[c4 + 0][r] = vq.x; sq[c4 + 1][r] = vq.y;
            sq[c4 + 2][r] = vq.z; sq[c4 + 3][r] = vq.w;
            float4 vh = *(const float4*)(Eh + (size_t)r * H_ + k0 + c4);
            sh[c4 + 0][r] = vh.x; sh[c4 + 1][r] = vh.y;
            sh[c4 + 2][r] = vh.z; sh[c4 + 3][r] = vh.w;
        }
        if (tid < 16)
            *(float4*)&sw[tid << 2] = *(const float4*)(W_att + k0 + (tid << 2));
        __syncthreads();

        #pragma unroll 8
        for (int kk = 0; kk < 64; kk++) {
            float qa = sq[kk][q0], qb = sq[kk][q0 + 16];
            float ha = sh[kk][h0], hb = sh[kk][h0 + 16];
            float w  = sw[kk];
            float p;
            p = qa * ha; s00 += p * w; n00 += p * p;
            p = qa * hb; s01 += p * w; n01 += p * p;
            p = qb * ha; s10 += p * w; n10 += p * p;
            p = qb * hb; s11 += p * w; n11 += p * p;
        }
        __syncthreads();
    }

    const float batt = b_att_p[0];
    ss[q0     ][h0     ] = s00 / fmaxf(sqrtf(n00), 1e-12f) + batt;
    ss[q0     ][h0 + 16] = s01 / fmaxf(sqrtf(n01), 1e-12f) + batt;
    ss[q0 + 16][h0     ] = s10 / fmaxf(sqrtf(n10), 1e-12f) + batt;
    ss[q0 + 16][h0 + 16] = s11 / fmaxf(sqrtf(n11), 1e-12f) + batt;
    __syncthreads();

    // Masked softmax over h <= q: 8 warps x 4 rows each, lane = h
    #pragma unroll
    for (int r = 0; r < 4; r++) {
        int q = warp * 4 + r;
        float x = ss[q][lane];
        bool valid = (lane <= q);
        float xm = valid ? x : -1e30f;
        #pragma unroll
        for (int off = 16; off; off >>= 1)
            xm = fmaxf(xm, __shfl_xor_sync(0xffffffffu, xm, off));
        float e = valid ? expf(x - xm) : 0.f;
        float se = e;
        #pragma unroll
        for (int off = 16; off; off >>= 1)
            se += __shfl_xor_sync(0xffffffffu, se, off);
        g_att[b][q][lane] = e / se;
    }
}

// ---------------------------------------------------------------------------
// Kernel C: feat[b,q,d] = sum_h att[b,q,h] * hist[b,h,d]   (d over IN_=2048)
// grid (8 d-chunks of 256, 64 batches), 256 threads; att & hist chunk in smem.
// ---------------------------------------------------------------------------
__global__ __launch_bounds__(256)
void feat_kernel(const float* __restrict__ hist, float* __restrict__ out)
{
    const int b   = blockIdx.y;
    const int d0  = blockIdx.x * 256;
    const int tid = threadIdx.x;

    __shared__ __align__(16) float s_att[32][32];
    __shared__ __align__(16) float s_hist[32][256];

    ((float4*)s_att)[tid] = ((const float4*)&g_att[b][0][0])[tid];
    #pragma unroll
    for (int i = 0; i < 8; i++) {
        int idx = tid + i * 256;           // 0..2047 float4 units
        int h   = idx >> 6;                // 0..31
        int c4  = (idx & 63) << 2;         // 0..1020
        *(float4*)&s_hist[h][c4] =
            *(const float4*)(hist + (size_t)(b * R_ + h) * IN_ + d0 + c4);
    }
    __syncthreads();

    float acc[32];
    #pragma unroll
    for (int q = 0; q < 32; q++) acc[q] = 0.f;
    #pragma unroll
    for (int h = 0; h < 32; h++) {
        float hv = s_hist[h][tid];
        #pragma unroll
        for (int q = 0; q < 32; q++)
            acc[q] += s_att[q][h] * hv;
    }
    #pragma unroll
    for (int q = 0; q < 32; q++)
        out[(size_t)(b * R_ + q) * IN_ + d0 + tid] = acc[q];
}

// ---------------------------------------------------------------------------
extern "C" void kernel_launch(void* const* d_in, const int* in_sizes, int n_in,
                              void* d_out, int out_size)
{
    const float* hist = (const float*)d_in[0];
    const float* ques = (const float*)d_in[1];
    const float* Why  = (const float*)d_in[2];
    const float* bhy  = (const float*)d_in[3];
    const float* Whg  = (const float*)d_in[4];
    const float* bhg  = (const float*)d_in[5];
    const float* Wqy  = (const float*)d_in[6];
    const float* bqy  = (const float*)d_in[7];
    const float* Wqg  = (const float*)d_in[8];
    const float* bqg  = (const float*)d_in[9];
    const float* Watt = (const float*)d_in[10];
    const float* batt = (const float*)d_in[11];
    float* out = (float*)d_out;

    dim3 gA(M_ / BM, H_ / BN, 2);          // (16, 16, 2)
    embed_kernel<<<gA, 256>>>(hist, ques, Why, bhy, Whg, bhg, Wqy, bqy, Wqg, bqg);

    score_kernel<<<B_, 256>>>(Watt, batt);

    dim3 gC(IN_ / 256, B_);                // (8, 64)
    feat_kernel<<<gC, 256>>>(hist, out);
}

// round 3
// speedup vs baseline: 3.6151x; 3.6151x over previous
#include <cuda_runtime.h>
#include <cuda_fp16.h>
#include <cstdint>
#include <math.h>

#define B_  64
#define R_  32
#define H_  1024
#define IN_ 2048
#define M_  (B_*R_)

// ---------------- scratch (__device__ globals) -----------------------------
__device__ __align__(16) float g_E[2][M_][H_];            // embeds fp32
__device__ __align__(16) float g_att[B_][R_][R_];         // softmax weights
__device__ __align__(16) __half g_Xf[2][M_][IN_];         // A fp16 [M,K]
__device__ __align__(16) __half g_Wf[4][H_][IN_];         // B fp16 [N,K] (W^T)

// ---------------- helpers --------------------------------------------------
__device__ __forceinline__ uint32_t smem_u32(const void* p){
    uint32_t a;
    asm("{ .reg .u64 t; cvta.to.shared.u64 t, %1; cvt.u32.u64 %0, t; }" : "=r"(a) : "l"(p));
    return a;
}
__device__ __forceinline__ void cpasync16(uint32_t dst, const void* src){
    asm volatile("cp.async.cg.shared.global [%0], [%1], 16;" :: "r"(dst), "l"(src));
}
#define CP_COMMIT() asm volatile("cp.async.commit_group;" ::: "memory")

#define LDSM_X4(d0,d1,d2,d3,addr) \
    asm volatile("ldmatrix.sync.aligned.m8n8.x4.shared.b16 {%0,%1,%2,%3}, [%4];" \
        : "=r"(d0),"=r"(d1),"=r"(d2),"=r"(d3) : "r"(addr))

#define MMA16816(c, a, b) \
    asm volatile("mma.sync.aligned.m16n8k16.row.col.f32.f16.f16.f32 " \
        "{%0,%1,%2,%3}, {%4,%5,%6,%7}, {%8,%9}, {%0,%1,%2,%3};" \
        : "+f"((c)[0]),"+f"((c)[1]),"+f"((c)[2]),"+f"((c)[3]) \
        : "r"((a)[0]),"r"((a)[1]),"r"((a)[2]),"r"((a)[3]), "r"((b)[0]),"r"((b)[1]))

// ---------------------------------------------------------------------------
// conv X: fp32 -> fp16, layout unchanged ([M,K])
// ---------------------------------------------------------------------------
__global__ __launch_bounds__(256)
void convX_kernel(const float* __restrict__ hist, const float* __restrict__ ques)
{
    int z = blockIdx.y;
    const float* X = z ? ques : hist;
    __half* dst = &g_Xf[z][0][0];
    size_t i = ((size_t)blockIdx.x * 256 + threadIdx.x) * 8;
    float4 v0 = *(const float4*)(X + i);
    float4 v1 = *(const float4*)(X + i + 4);
    __half2 h[4];
    h[0] = __floats2half2_rn(v0.x, v0.y);
    h[1] = __floats2half2_rn(v0.z, v0.w);
    h[2] = __floats2half2_rn(v1.x, v1.y);
    h[3] = __floats2half2_rn(v1.z, v1.w);
    *(uint4*)(dst + i) = *(uint4*)h;
}

// ---------------------------------------------------------------------------
// conv W: W[K,N] fp32 -> Wt[N,K] fp16 (transpose via smem)
// ---------------------------------------------------------------------------
__global__ __launch_bounds__(256)
void convW_kernel(const float* __restrict__ W0, const float* __restrict__ W1,
                  const float* __restrict__ W2, const float* __restrict__ W3)
{
    const float* Ws[4] = {W0, W1, W2, W3};
    const int br = blockIdx.z;
    const float* W = Ws[br];
    __shared__ float s[64][65];
    const int k0 = blockIdx.x * 64, n0 = blockIdx.y * 64;
    const int tid = threadIdx.x;

    #pragma unroll
    for (int i = 0; i < 4; i++){
        int idx = tid + i * 256;
        int r = idx >> 4;
        int c = (idx & 15) * 4;
        float4 v = *(const float4*)(W + (size_t)(k0 + r) * H_ + n0 + c);
        s[r][c] = v.x; s[r][c+1] = v.y; s[r][c+2] = v.z; s[r][c+3] = v.w;
    }
    __syncthreads();

    int nl  = tid >> 2;          // 0..63 output row (n)
    int seg = (tid & 3) * 16;    // k segment
    __half2 h[8];
    #pragma unroll
    for (int j = 0; j < 8; j++)
        h[j] = __floats2half2_rn(s[seg + 2*j][nl], s[seg + 2*j + 1][nl]);
    __half* o = &g_Wf[br][n0 + nl][k0 + seg];
    *(uint4*)(o)     = *(uint4*)&h[0];
    *(uint4*)(o + 8) = *(uint4*)&h[4];
}

// ---------------------------------------------------------------------------
// embed GEMM: HMMA m16n8k16 fp16, fused dual-branch, cp.async 2-stage pipe.
// CTA: BM=128, BN=64 per branch, BK=32. 256 threads = 8 warps (4m x 2n),
// warp tile 32x32 per branch. Epilogue: bias + tanh*leaky_relu -> g_E fp32.
// ---------------------------------------------------------------------------
__global__ __launch_bounds__(256, 2)
void embed_hmma_kernel(const float* __restrict__ bhy, const float* __restrict__ bhg,
                       const float* __restrict__ bqy, const float* __restrict__ bqg)
{
    __shared__ __align__(16) __half sA[2][128 * 40];     // pitch 40 halves (80B)
    __shared__ __align__(16) __half sB[2][2][64 * 40];

    const int tid  = threadIdx.x;
    const int lane = tid & 31, wid = tid >> 5;
    const int wm = wid >> 1, wn = wid & 1;
    const int z  = blockIdx.z;
    const int m0 = blockIdx.x * 128;
    const int n0 = blockIdx.y * 64;

    const __half* Xf = &g_Xf[z][0][0];
    const __half* Wy = &g_Wf[2*z + 0][0][0];
    const __half* Wg = &g_Wf[2*z + 1][0][0];

    const uint32_t sAu = smem_u32(&sA[0][0]);
    const uint32_t sBu = smem_u32(&sB[0][0][0]);

    float acc[2][2][4][4];
    #pragma unroll
    for (int b = 0; b < 2; b++)
        #pragma unroll
        for (int mi = 0; mi < 2; mi++)
            #pragma unroll
            for (int ni = 0; ni < 4; ni++)
                #pragma unroll
                for (int r = 0; r < 4; r++) acc[b][mi][ni][r] = 0.f;

    // ---- stage loader (cp.async) ----
    auto load_stage = [&](int s){
        const int k0 = s * 32, buf = s & 1;
        #pragma unroll
        for (int i = 0; i < 2; i++){           // A: 512 chunks of 16B
            int idx = tid + i * 256;
            int row = idx >> 2, seg = idx & 3;
            uint32_t dst = sAu + buf * 10240 + (row * 40 + seg * 8) * 2;
            cpasync16(dst, Xf + (size_t)(m0 + row) * IN_ + k0 + seg * 8);
        }
        #pragma unroll
        for (int i = 0; i < 2; i++){           // B: 2 branches x 256 chunks
            int idx = tid + i * 256;
            int t = idx >> 8, r = (idx >> 2) & 63, seg = idx & 3;
            const __half* W = t ? Wg : Wy;
            uint32_t dst = sBu + buf * 10240 + t * 5120 + (r * 40 + seg * 8) * 2;
            cpasync16(dst, W + (size_t)(n0 + r) * IN_ + k0 + seg * 8);
        }
    };

    load_stage(0);
    CP_COMMIT();

    const int lr = lane & 15;        // ldmatrix row-within-16
    const int lc = (lane >> 4) * 8;  // ldmatrix k-offset 0/8

    for (int s = 0; s < 64; s++){
        const int buf = s & 1;
        if (s < 63){
            load_stage(s + 1);
            CP_COMMIT();
            asm volatile("cp.async.wait_group 1;" ::: "memory");
        } else {
            asm volatile("cp.async.wait_group 0;" ::: "memory");
        }
        __syncthreads();

        const uint32_t aBase = sAu + buf * 10240;
        const uint32_t bBase = sBu + buf * 10240;

        #pragma unroll
        for (int kk = 0; kk < 32; kk += 16){
            uint32_t a[2][4];
            #pragma unroll
            for (int mi = 0; mi < 2; mi++){
                uint32_t ad = aBase + ((wm*32 + mi*16 + lr) * 40 + kk + lc) * 2;
                LDSM_X4(a[mi][0], a[mi][1], a[mi][2], a[mi][3], ad);
            }
            #pragma unroll
            for (int br = 0; br < 2; br++){
                uint32_t bb[4][2];
                #pragma unroll
                for (int hn = 0; hn < 2; hn++){
                    uint32_t t0, t1, t2, t3;
                    uint32_t bd = bBase + br * 5120 +
                                  ((wn*32 + hn*16 + lr) * 40 + kk + lc) * 2;
                    LDSM_X4(t0, t1, t2, t3, bd);
                    bb[2*hn  ][0] = t0; bb[2*hn  ][1] = t2;
                    bb[2*hn+1][0] = t1; bb[2*hn+1][1] = t3;
                }
                #pragma unroll
                for (int mi = 0; mi < 2; mi++)
                    #pragma unroll
                    for (int ni = 0; ni < 4; ni++)
                        MMA16816(acc[br][mi][ni], a[mi], bb[ni]);
            }
        }
        __syncthreads();
    }

    // ---- epilogue ----
    const float* by = z ? bqy : bhy;
    const float* bg = z ? bqg : bhg;
    const int grp = lane >> 2, tig = lane & 3;
    #pragma unroll
    for (int mi = 0; mi < 2; mi++){
        #pragma unroll
        for (int ni = 0; ni < 4; ni++){
            const float* ay = acc[0][mi][ni];
            const float* ag = acc[1][mi][ni];
            const int gn  = n0 + wn*32 + ni*8 + tig*2;
            const int gm0 = m0 + wm*32 + mi*16 + grp;
            const float by0 = by[gn], by1 = by[gn+1];
            const float bg0 = bg[gn], bg1 = bg[gn+1];
            float2 o0, o1;
            {
                float g0 = ag[0] + bg0; g0 = g0 > 0.f ? g0 : 0.01f * g0;
                float g1 = ag[1] + bg1; g1 = g1 > 0.f ? g1 : 0.01f * g1;
                o0.x = tanhf(ay[0] + by0) * g0;
                o0.y = tanhf(ay[1] + by1) * g1;
            }
            {
                float g0 = ag[2] + bg0; g0 = g0 > 0.f ? g0 : 0.01f * g0;
                float g1 = ag[3] + bg1; g1 = g1 > 0.f ? g1 : 0.01f * g1;
                o1.x = tanhf(ay[2] + by0) * g0;
                o1.y = tanhf(ay[3] + by1) * g1;
            }
            *(float2*)&g_E[z][gm0    ][gn] = o0;
            *(float2*)&g_E[z][gm0 + 8][gn] = o1;
        }
    }
}

// ---------------------------------------------------------------------------
// Kernel B: per-batch scores + masked softmax (unchanged, passing).
// ---------------------------------------------------------------------------
__global__ __launch_bounds__(256)
void score_kernel(const float* __restrict__ W_att, const float* __restrict__ b_att_p)
{
    const int b    = blockIdx.x;
    const int tid  = threadIdx.x;
    const int lane = tid & 31;
    const int warp = tid >> 5;

    __shared__ float sq[64][33];
    __shared__ float sh[64][33];
    __shared__ __align__(16) float sw[64];
    __shared__ float ss[32][33];

    const int q0 = tid >> 4;
    const int h0 = tid & 15;

    float s00 = 0.f, s01 = 0.f, s10 = 0.f, s11 = 0.f;
    float n00 = 0.f, n01 = 0.f, n10 = 0.f, n11 = 0.f;

    const float* Eq = &g_E[1][b * R_][0];
    const float* Eh = &g_E[0][b * R_][0];

    for (int k0 = 0; k0 < H_; k0 += 64) {
        #pragma unroll
        for (int i = 0; i < 2; i++) {
            int idx = tid + i * 256;
            int r   = idx >> 4;
            int c4  = (idx & 15) << 2;
            float4 vq = *(const float4*)(Eq + (size_t)r * H_ + k0 + c4);
            sq[c4 + 0][r] = vq.x; sq[c4 + 1][r] = vq.y;
            sq[c4 + 2][r] = vq.z; sq[c4 + 3][r] = vq.w;
            float4 vh = *(const float4*)(Eh + (size_t)r * H_ + k0 + c4);
            sh[c4 + 0][r] = vh.x; sh[c4 + 1][r] = vh.y;
            sh[c4 + 2][r] = vh.z; sh[c4 + 3][r] = vh.w;
        }
        if (tid < 16)
            *(float4*)&sw[tid << 2] = *(const float4*)(W_att + k0 + (tid << 2));
        __syncthreads();

        #pragma unroll 8
        for (int kk = 0; kk < 64; kk++) {
            float qa = sq[kk][q0], qb = sq[kk][q0 + 16];
            float ha = sh[kk][h0], hb = sh[kk][h0 + 16];
            float w  = sw[kk];
            float p;
            p = qa * ha; s00 += p * w; n00 += p * p;
            p = qa * hb; s01 += p * w; n01 += p * p;
            p = qb * ha; s10 += p * w; n10 += p * p;
            p = qb * hb; s11 += p * w; n11 += p * p;
        }
        __syncthreads();
    }

    const float batt = b_att_p[0];
    ss[q0     ][h0     ] = s00 / fmaxf(sqrtf(n00), 1e-12f) + batt;
    ss[q0     ][h0 + 16] = s01 / fmaxf(sqrtf(n01), 1e-12f) + batt;
    ss[q0 + 16][h0     ] = s10 / fmaxf(sqrtf(n10), 1e-12f) + batt;
    ss[q0 + 16][h0 + 16] = s11 / fmaxf(sqrtf(n11), 1e-12f) + batt;
    __syncthreads();

    #pragma unroll
    for (int r = 0; r < 4; r++) {
        int q = warp * 4 + r;
        float x = ss[q][lane];
        bool valid = (lane <= q);
        float xm = valid ? x : -1e30f;
        #pragma unroll
        for (int off = 16; off; off >>= 1)
            xm = fmaxf(xm, __shfl_xor_sync(0xffffffffu, xm, off));
        float e = valid ? expf(x - xm) : 0.f;
        float se = e;
        #pragma unroll
        for (int off = 16; off; off >>= 1)
            se += __shfl_xor_sync(0xffffffffu, se, off);
        g_att[b][q][lane] = e / se;
    }
}

// ---------------------------------------------------------------------------
// Kernel C: feat = att @ hist (unchanged, passing).
// ---------------------------------------------------------------------------
__global__ __launch_bounds__(256)
void feat_kernel(const float* __restrict__ hist, float* __restrict__ out)
{
    const int b   = blockIdx.y;
    const int d0  = blockIdx.x * 256;
    const int tid = threadIdx.x;

    __shared__ __align__(16) float s_att[32][32];
    __shared__ __align__(16) float s_hist[32][256];

    ((float4*)s_att)[tid] = ((const float4*)&g_att[b][0][0])[tid];
    #pragma unroll
    for (int i = 0; i < 8; i++) {
        int idx = tid + i * 256;
        int h   = idx >> 6;
        int c4  = (idx & 63) << 2;
        *(float4*)&s_hist[h][c4] =
            *(const float4*)(hist + (size_t)(b * R_ + h) * IN_ + d0 + c4);
    }
    __syncthreads();

    float acc[32];
    #pragma unroll
    for (int q = 0; q < 32; q++) acc[q] = 0.f;
    #pragma unroll
    for (int h = 0; h < 32; h++) {
        float hv = s_hist[h][tid];
        #pragma unroll
        for (int q = 0; q < 32; q++)
            acc[q] += s_att[q][h] * hv;
    }
    #pragma unroll
    for (int q = 0; q < 32; q++)
        out[(size_t)(b * R_ + q) * IN_ + d0 + tid] = acc[q];
}

// ---------------------------------------------------------------------------
extern "C" void kernel_launch(void* const* d_in, const int* in_sizes, int n_in,
                              void* d_out, int out_size)
{
    const float* hist = (const float*)d_in[0];
    const float* ques = (const float*)d_in[1];
    const float* Why  = (const float*)d_in[2];
    const float* bhy  = (const float*)d_in[3];
    const float* Whg  = (const float*)d_in[4];
    const float* bhg  = (const float*)d_in[5];
    const float* Wqy  = (const float*)d_in[6];
    const float* bqy  = (const float*)d_in[7];
    const float* Wqg  = (const float*)d_in[8];
    const float* bqg  = (const float*)d_in[9];
    const float* Watt = (const float*)d_in[10];
    const float* batt = (const float*)d_in[11];
    float* out = (float*)d_out;

    convX_kernel<<<dim3(2048, 2), 256>>>(hist, ques);
    convW_kernel<<<dim3(32, 16, 4), 256>>>(Why, Whg, Wqy, Wqg);
    embed_hmma_kernel<<<dim3(16, 16, 2), 256>>>(bhy, bhg, bqy, bqg);
    score_kernel<<<B_, 256>>>(Watt, batt);
    feat_kernel<<<dim3(IN_ / 256, B_), 256>>>(hist, out);
}

// round 5
// speedup vs baseline: 4.1112x; 1.1372x over previous
#include <cuda_runtime.h>
#include <cuda_fp16.h>
#include <cstdint>
#include <math.h>

#define B_  64
#define R_  32
#define H_  1024
#define IN_ 2048
#define M_  (B_*R_)
#define KSL 4                 // score k-slices
#define KCH (H_/KSL)          // 256 k per slice

// ---------------- scratch (__device__ globals) -----------------------------
__device__ __align__(16) float g_E[2][M_][H_];            // embeds fp32
__device__ __align__(16) float g_att[B_][R_][R_];         // softmax weights
__device__ __align__(16) __half g_Xf[2][M_][IN_];         // A fp16 [M,K]
__device__ __align__(16) __half g_Wf[4][H_][IN_];         // B fp16 [N,K] (W^T)
__device__ __align__(16) float g_spart[KSL][B_][R_][R_];  // partial scores
__device__ __align__(16) float g_npart[KSL][B_][R_][R_];  // partial norms

// ---------------- helpers --------------------------------------------------
__device__ __forceinline__ uint32_t smem_u32(const void* p){
    uint32_t a;
    asm("{ .reg .u64 t; cvta.to.shared.u64 t, %1; cvt.u32.u64 %0, t; }" : "=r"(a) : "l"(p));
    return a;
}
__device__ __forceinline__ void cpasync16(uint32_t dst, const void* src){
    asm volatile("cp.async.cg.shared.global [%0], [%1], 16;" :: "r"(dst), "l"(src));
}
#define CP_COMMIT() asm volatile("cp.async.commit_group;" ::: "memory")

#define LDSM_X4(d0,d1,d2,d3,addr) \
    asm volatile("ldmatrix.sync.aligned.m8n8.x4.shared.b16 {%0,%1,%2,%3}, [%4];" \
        : "=r"(d0),"=r"(d1),"=r"(d2),"=r"(d3) : "r"(addr))

#define MMA16816(c, a, b) \
    asm volatile("mma.sync.aligned.m16n8k16.row.col.f32.f16.f16.f32 " \
        "{%0,%1,%2,%3}, {%4,%5,%6,%7}, {%8,%9}, {%0,%1,%2,%3};" \
        : "+f"((c)[0]),"+f"((c)[1]),"+f"((c)[2]),"+f"((c)[3]) \
        : "r"((a)[0]),"r"((a)[1]),"r"((a)[2]),"r"((a)[3]), "r"((b)[0]),"r"((b)[1]))

// ---------------------------------------------------------------------------
// conv X: fp32 -> fp16
// ---------------------------------------------------------------------------
__global__ __launch_bounds__(256)
void convX_kernel(const float* __restrict__ hist, const float* __restrict__ ques)
{
    int z = blockIdx.y;
    const float* X = z ? ques : hist;
    __half* dst = &g_Xf[z][0][0];
    size_t i = ((size_t)blockIdx.x * 256 + threadIdx.x) * 8;
    float4 v0 = *(const float4*)(X + i);
    float4 v1 = *(const float4*)(X + i + 4);
    __half2 h[4];
    h[0] = __floats2half2_rn(v0.x, v0.y);
    h[1] = __floats2half2_rn(v0.z, v0.w);
    h[2] = __floats2half2_rn(v1.x, v1.y);
    h[3] = __floats2half2_rn(v1.z, v1.w);
    *(uint4*)(dst + i) = *(uint4*)h;
}

// ---------------------------------------------------------------------------
// conv W: W[K,N] fp32 -> Wt[N,K] fp16 (transpose via smem)
// ---------------------------------------------------------------------------
__global__ __launch_bounds__(256)
void convW_kernel(const float* __restrict__ W0, const float* __restrict__ W1,
                  const float* __restrict__ W2, const float* __restrict__ W3)
{
    const float* Ws[4] = {W0, W1, W2, W3};
    const int br = blockIdx.z;
    const float* W = Ws[br];
    __shared__ float s[64][65];
    const int k0 = blockIdx.x * 64, n0 = blockIdx.y * 64;
    const int tid = threadIdx.x;

    #pragma unroll
    for (int i = 0; i < 4; i++){
        int idx = tid + i * 256;
        int r = idx >> 4;
        int c = (idx & 15) * 4;
        float4 v = *(const float4*)(W + (size_t)(k0 + r) * H_ + n0 + c);
        s[r][c] = v.x; s[r][c+1] = v.y; s[r][c+2] = v.z; s[r][c+3] = v.w;
    }
    __syncthreads();

    int nl  = tid >> 2;
    int seg = (tid & 3) * 16;
    __half2 h[8];
    #pragma unroll
    for (int j = 0; j < 8; j++)
        h[j] = __floats2half2_rn(s[seg + 2*j][nl], s[seg + 2*j + 1][nl]);
    __half* o = &g_Wf[br][n0 + nl][k0 + seg];
    *(uint4*)(o)     = *(uint4*)&h[0];
    *(uint4*)(o + 8) = *(uint4*)&h[4];
}

// ---------------------------------------------------------------------------
// embed GEMM: HMMA m16n8k16 fp16, fused dual-branch, 3-stage cp.async pipe,
// ONE __syncthreads per K-iteration (3 buffers break the WAR collision).
// CTA: BM=128, BN=64/branch, BK=32. 8 warps (4m x 2n), warp tile 32x32 x2.
// ---------------------------------------------------------------------------
#define ST_A   10240                     // 128 * 40 halves * 2B
#define ST_B   10240                     // 2 * 64 * 40 * 2B
#define ST_TOT (ST_A + ST_B)             // 20480 per stage
#define EMB_SMEM (3 * ST_TOT)            // 61440

__global__ __launch_bounds__(256, 2)
void embed_hmma_kernel(const float* __restrict__ bhy, const float* __restrict__ bhg,
                       const float* __restrict__ bqy, const float* __restrict__ bqg)
{
    extern __shared__ __align__(16) char sm[];
    const uint32_t smu = smem_u32(sm);

    const int tid  = threadIdx.x;
    const int lane = tid & 31, wid = tid >> 5;
    const int wm = wid >> 1, wn = wid & 1;
    const int z  = blockIdx.z;
    const int m0 = blockIdx.x * 128;
    const int n0 = blockIdx.y * 64;

    const __half* Xf = &g_Xf[z][0][0];
    const __half* Wy = &g_Wf[2*z + 0][0][0];
    const __half* Wg = &g_Wf[2*z + 1][0][0];

    float acc[2][2][4][4];
    #pragma unroll
    for (int b = 0; b < 2; b++)
        #pragma unroll
        for (int mi = 0; mi < 2; mi++)
            #pragma unroll
            for (int ni = 0; ni < 4; ni++)
                #pragma unroll
                for (int r = 0; r < 4; r++) acc[b][mi][ni][r] = 0.f;

    auto load_stage = [&](int s){
        const int k0 = s * 32, buf = s % 3;
        const uint32_t base = smu + buf * ST_TOT;
        #pragma unroll
        for (int i = 0; i < 2; i++){           // A: 512 x 16B
            int idx = tid + i * 256;
            int row = idx >> 2, seg = idx & 3;
            cpasync16(base + (row * 40 + seg * 8) * 2,
                      Xf + (size_t)(m0 + row) * IN_ + k0 + seg * 8);
        }
        #pragma unroll
        for (int i = 0; i < 2; i++){           // B: 2 branches x 256 x 16B
            int idx = tid + i * 256;
            int t = idx >> 8, r = (idx >> 2) & 63, seg = idx & 3;
            const __half* W = t ? Wg : Wy;
            cpasync16(base + ST_A + t * 5120 + (r * 40 + seg * 8) * 2,
                      W + (size_t)(n0 + r) * IN_ + k0 + seg * 8);
        }
    };

    load_stage(0); CP_COMMIT();
    load_stage(1); CP_COMMIT();

    const int lr = lane & 15;
    const int lc = (lane >> 4) * 8;

    for (int s = 0; s < 64; s++){
        if (s + 2 < 64) load_stage(s + 2);
        CP_COMMIT();                                  // uniform group cadence
        asm volatile("cp.async.wait_group 2;" ::: "memory");
        __syncthreads();

        const uint32_t base  = smu + (s % 3) * ST_TOT;
        const uint32_t bBase = base + ST_A;

        #pragma unroll
        for (int kk = 0; kk < 32; kk += 16){
            uint32_t a[2][4];
            #pragma unroll
            for (int mi = 0; mi < 2; mi++){
                uint32_t ad = base + ((wm*32 + mi*16 + lr) * 40 + kk + lc) * 2;
                LDSM_X4(a[mi][0], a[mi][1], a[mi][2], a[mi][3], ad);
            }
            #pragma unroll
            for (int br = 0; br < 2; br++){
                uint32_t bb[4][2];
                #pragma unroll
                for (int hn = 0; hn < 2; hn++){
                    uint32_t t0, t1, t2, t3;
                    uint32_t bd = bBase + br * 5120 +
                                  ((wn*32 + hn*16 + lr) * 40 + kk + lc) * 2;
                    LDSM_X4(t0, t1, t2, t3, bd);
                    bb[2*hn  ][0] = t0; bb[2*hn  ][1] = t2;
                    bb[2*hn+1][0] = t1; bb[2*hn+1][1] = t3;
                }
                #pragma unroll
                for (int mi = 0; mi < 2; mi++)
                    #pragma unroll
                    for (int ni = 0; ni < 4; ni++)
                        MMA16816(acc[br][mi][ni], a[mi], bb[ni]);
            }
        }
    }

    const float* by = z ? bqy : bhy;
    const float* bg = z ? bqg : bhg;
    const int grp = lane >> 2, tig = lane & 3;
    #pragma unroll
    for (int mi = 0; mi < 2; mi++){
        #pragma unroll
        for (int ni = 0; ni < 4; ni++){
            const float* ay = acc[0][mi][ni];
            const float* ag = acc[1][mi][ni];
            const int gn  = n0 + wn*32 + ni*8 + tig*2;
            const int gm0 = m0 + wm*32 + mi*16 + grp;
            const float by0 = by[gn], by1 = by[gn+1];
            const float bg0 = bg[gn], bg1 = bg[gn+1];
            float2 o0, o1;
            {
                float g0 = ag[0] + bg0; g0 = g0 > 0.f ? g0 : 0.01f * g0;
                float g1 = ag[1] + bg1; g1 = g1 > 0.f ? g1 : 0.01f * g1;
                o0.x = tanhf(ay[0] + by0) * g0;
                o0.y = tanhf(ay[1] + by1) * g1;
            }
            {
                float g0 = ag[2] + bg0; g0 = g0 > 0.f ? g0 : 0.01f * g0;
                float g1 = ag[3] + bg1; g1 = g1 > 0.f ? g1 : 0.01f * g1;
                o1.x = tanhf(ay[2] + by0) * g0;
                o1.y = tanhf(ay[3] + by1) * g1;
            }
            *(float2*)&g_E[z][gm0    ][gn] = o0;
            *(float2*)&g_E[z][gm0 + 8][gn] = o1;
        }
    }
}

// ---------------------------------------------------------------------------
// score partial: grid (KSL, B_). Block computes 32x32 partial s/n over KCH k.
// ---------------------------------------------------------------------------
__global__ __launch_bounds__(256)
void score_part_kernel(const float* __restrict__ W_att)
{
    const int sl = blockIdx.x;
    const int b  = blockIdx.y;
    const int tid = threadIdx.x;
    const int kbase = sl * KCH;

    __shared__ float sq[64][33];
    __shared__ float sh[64][33];
    __shared__ __align__(16) float sw[64];

    const int q0 = tid >> 4;
    const int h0 = tid & 15;

    float s00 = 0.f, s01 = 0.f, s10 = 0.f, s11 = 0.f;
    float n00 = 0.f, n01 = 0.f, n10 = 0.f, n11 = 0.f;

    const float* Eq = &g_E[1][b * R_][0];
    const float* Eh = &g_E[0][b * R_][0];

    for (int k0 = kbase; k0 < kbase + KCH; k0 += 64) {
        #pragma unroll
        for (int i = 0; i < 2; i++) {
            int idx = tid + i * 256;
            int r   = idx >> 4;
            int c4  = (idx & 15) << 2;
            float4 vq = *(const float4*)(Eq + (size_t)r * H_ + k0 + c4);
            sq[c4 + 0][r] = vq.x; sq[c4 + 1][r] = vq.y;
            sq[c4 + 2][r] = vq.z; sq[c4 + 3][r] = vq.w;
            float4 vh = *(const float4*)(Eh + (size_t)r * H_ + k0 + c4);
            sh[c4 + 0][r] = vh.x; sh[c4 + 1][r] = vh.y;
            sh[c4 + 2][r] = vh.z; sh[c4 + 3][r] = vh.w;
        }
        if (tid < 16)
            *(float4*)&sw[tid << 2] = *(const float4*)(W_att + k0 + (tid << 2));
        __syncthreads();

        #pragma unroll 8
        for (int kk = 0; kk < 64; kk++) {
            float qa = sq[kk][q0], qb = sq[kk][q0 + 16];
            float ha = sh[kk][h0], hb = sh[kk][h0 + 16];
            float w  = sw[kk];
            float p;
            p = qa * ha; s00 += p * w; n00 += p * p;
            p = qa * hb; s01 += p * w; n01 += p * p;
            p = qb * ha; s10 += p * w; n10 += p * p;
            p = qb * hb; s11 += p * w; n11 += p * p;
        }
        __syncthreads();
    }

    g_spart[sl][b][q0     ][h0     ] = s00;
    g_spart[sl][b][q0     ][h0 + 16] = s01;
    g_spart[sl][b][q0 + 16][h0     ] = s10;
    g_spart[sl][b][q0 + 16][h0 + 16] = s11;
    g_npart[sl][b][q0     ][h0     ] = n00;
    g_npart[sl][b][q0     ][h0 + 16] = n01;
    g_npart[sl][b][q0 + 16][h0     ] = n10;
    g_npart[sl][b][q0 + 16][h0 + 16] = n11;
}

// ---------------------------------------------------------------------------
// score combine + masked softmax: grid B_, block 1024 (warp = q row, lane = h)
// ---------------------------------------------------------------------------
__global__ __launch_bounds__(1024)
void score_comb_kernel(const float* __restrict__ b_att_p)
{
    const int b = blockIdx.x;
    const int q = threadIdx.x >> 5;
    const int h = threadIdx.x & 31;

    float s = 0.f, n = 0.f;
    #pragma unroll
    for (int sl = 0; sl < KSL; sl++){
        s += g_spart[sl][b][q][h];
        n += g_npart[sl][b][q][h];
    }
    float x = s / fmaxf(sqrtf(n), 1e-12f) + b_att_p[0];

    bool valid = (h <= q);
    float xm = valid ? x : -1e30f;
    #pragma unroll
    for (int off = 16; off; off >>= 1)
        xm = fmaxf(xm, __shfl_xor_sync(0xffffffffu, xm, off));
    float e = valid ? expf(x - xm) : 0.f;
    float se = e;
    #pragma unroll
    for (int off = 16; off; off >>= 1)
        se += __shfl_xor_sync(0xffffffffu, se, off);
    g_att[b][q][h] = e / se;
}

// ---------------------------------------------------------------------------
// Kernel C: feat = att @ hist (unchanged, passing).
// ---------------------------------------------------------------------------
__global__ __launch_bounds__(256)
void feat_kernel(const float* __restrict__ hist, float* __restrict__ out)
{
    const int b   = blockIdx.y;
    const int d0  = blockIdx.x * 256;
    const int tid = threadIdx.x;

    __shared__ __align__(16) float s_att[32][32];
    __shared__ __align__(16) float s_hist[32][256];

    ((float4*)s_att)[tid] = ((const float4*)&g_att[b][0][0])[tid];
    #pragma unroll
    for (int i = 0; i < 8; i++) {
        int idx = tid + i * 256;
        int h   = idx >> 6;
        int c4  = (idx & 63) << 2;
        *(float4*)&s_hist[h][c4] =
            *(const float4*)(hist + (size_t)(b * R_ + h) * IN_ + d0 + c4);
    }
    __syncthreads();

    float acc[32];
    #pragma unroll
    for (int q = 0; q < 32; q++) acc[q] = 0.f;
    #pragma unroll
    for (int h = 0; h < 32; h++) {
        float hv = s_hist[h][tid];
        #pragma unroll
        for (int q = 0; q < 32; q++)
            acc[q] += s_att[q][h] * hv;
    }
    #pragma unroll
    for (int q = 0; q < 32; q++)
        out[(size_t)(b * R_ + q) * IN_ + d0 + tid] = acc[q];
}

// ---------------------------------------------------------------------------
extern "C" void kernel_launch(void* const* d_in, const int* in_sizes, int n_in,
                              void* d_out, int out_size)
{
    const float* hist = (const float*)d_in[0];
    const float* ques = (const float*)d_in[1];
    const float* Why  = (const float*)d_in[2];
    const float* bhy  = (const float*)d_in[3];
    const float* Whg  = (const float*)d_in[4];
    const float* bhg  = (const float*)d_in[5];
    const float* Wqy  = (const float*)d_in[6];
    const float* bqy  = (const float*)d_in[7];
    const float* Wqg  = (const float*)d_in[8];
    const float* bqg  = (const float*)d_in[9];
    const float* Watt = (const float*)d_in[10];
    const float* batt = (const float*)d_in[11];
    float* out = (float*)d_out;

    cudaFuncSetAttribute(embed_hmma_kernel,
                         cudaFuncAttributeMaxDynamicSharedMemorySize, EMB_SMEM);

    convX_kernel<<<dim3(2048, 2), 256>>>(hist, ques);
    convW_kernel<<<dim3(32, 16, 4), 256>>>(Why, Whg, Wqy, Wqg);
    embed_hmma_kernel<<<dim3(16, 16, 2), 256, EMB_SMEM>>>(bhy, bhg, bqy, bqg);
    score_part_kernel<<<dim3(KSL, B_), 256>>>(Watt);
    score_comb_kernel<<<B_, 1024>>>(batt);
    feat_kernel<<<dim3(IN_ / 256, B_), 256>>>(hist, out);
}

// round 6
// speedup vs baseline: 4.4308x; 1.0777x over previous
#include <cuda_runtime.h>
#include <cuda_fp16.h>
#include <cstdint>
#include <math.h>

#define B_  64
#define R_  32
#define H_  1024
#define IN_ 2048
#define M_  (B_*R_)
#define KSL 8                 // score k-slices
#define KCH (H_/KSL)          // 128 k per slice

// ---------------- scratch (__device__ globals) -----------------------------
__device__ __align__(16) float g_E[2][M_][H_];            // embeds fp32
__device__ __align__(16) float g_att[B_][R_][R_];         // softmax weights
__device__ __align__(16) __half g_Xf[2][M_][IN_];         // A fp16 [M,K]
__device__ __align__(16) __half g_Wf[4][H_][IN_];         // B fp16 [N,K] (W^T)
__device__ __align__(16) float g_spart[KSL][B_][R_][R_];  // partial scores
__device__ __align__(16) float g_npart[KSL][B_][R_][R_];  // partial norms

// ---------------- helpers --------------------------------------------------
__device__ __forceinline__ uint32_t smem_u32(const void* p){
    uint32_t a;
    asm("{ .reg .u64 t; cvta.to.shared.u64 t, %1; cvt.u32.u64 %0, t; }" : "=r"(a) : "l"(p));
    return a;
}
__device__ __forceinline__ void cpasync16(uint32_t dst, const void* src){
    asm volatile("cp.async.cg.shared.global [%0], [%1], 16;" :: "r"(dst), "l"(src));
}
#define CP_COMMIT() asm volatile("cp.async.commit_group;" ::: "memory")

#define LDSM_X4(d0,d1,d2,d3,addr) \
    asm volatile("ldmatrix.sync.aligned.m8n8.x4.shared.b16 {%0,%1,%2,%3}, [%4];" \
        : "=r"(d0),"=r"(d1),"=r"(d2),"=r"(d3) : "r"(addr))

#define MMA16816(c, a, b) \
    asm volatile("mma.sync.aligned.m16n8k16.row.col.f32.f16.f16.f32 " \
        "{%0,%1,%2,%3}, {%4,%5,%6,%7}, {%8,%9}, {%0,%1,%2,%3};" \
        : "+f"((c)[0]),"+f"((c)[1]),"+f"((c)[2]),"+f"((c)[3]) \
        : "r"((a)[0]),"r"((a)[1]),"r"((a)[2]),"r"((a)[3]), "r"((b)[0]),"r"((b)[1]))

// ---------------------------------------------------------------------------
// conv X: fp32 -> fp16
// ---------------------------------------------------------------------------
__global__ __launch_bounds__(256)
void convX_kernel(const float* __restrict__ hist, const float* __restrict__ ques)
{
    int z = blockIdx.y;
    const float* X = z ? ques : hist;
    __half* dst = &g_Xf[z][0][0];
    size_t i = ((size_t)blockIdx.x * 256 + threadIdx.x) * 8;
    float4 v0 = *(const float4*)(X + i);
    float4 v1 = *(const float4*)(X + i + 4);
    __half2 h[4];
    h[0] = __floats2half2_rn(v0.x, v0.y);
    h[1] = __floats2half2_rn(v0.z, v0.w);
    h[2] = __floats2half2_rn(v1.x, v1.y);
    h[3] = __floats2half2_rn(v1.z, v1.w);
    *(uint4*)(dst + i) = *(uint4*)h;
}

// ---------------------------------------------------------------------------
// conv W: W[K,N] fp32 -> Wt[N,K] fp16 (transpose via smem)
// ---------------------------------------------------------------------------
__global__ __launch_bounds__(256)
void convW_kernel(const float* __restrict__ W0, const float* __restrict__ W1,
                  const float* __restrict__ W2, const float* __restrict__ W3)
{
    const float* Ws[4] = {W0, W1, W2, W3};
    const int br = blockIdx.z;
    const float* W = Ws[br];
    __shared__ float s[64][65];
    const int k0 = blockIdx.x * 64, n0 = blockIdx.y * 64;
    const int tid = threadIdx.x;

    #pragma unroll
    for (int i = 0; i < 4; i++){
        int idx = tid + i * 256;
        int r = idx >> 4;
        int c = (idx & 15) * 4;
        float4 v = *(const float4*)(W + (size_t)(k0 + r) * H_ + n0 + c);
        s[r][c] = v.x; s[r][c+1] = v.y; s[r][c+2] = v.z; s[r][c+3] = v.w;
    }
    __syncthreads();

    int nl  = tid >> 2;
    int seg = (tid & 3) * 16;
    __half2 h[8];
    #pragma unroll
    for (int j = 0; j < 8; j++)
        h[j] = __floats2half2_rn(s[seg + 2*j][nl], s[seg + 2*j + 1][nl]);
    __half* o = &g_Wf[br][n0 + nl][k0 + seg];
    *(uint4*)(o)     = *(uint4*)&h[0];
    *(uint4*)(o + 8) = *(uint4*)&h[4];
}

// ---------------------------------------------------------------------------
// embed GEMM: HMMA m16n8k16 fp16, fused dual-branch, 3-stage cp.async pipe,
// BK=64 (one __syncthreads per 64-K), pitch 72 halves (conflict-free ldsm).
// CTA: BM=128, BN=64/branch. 8 warps (4m x 2n), warp tile 32x32 x2 branches.
// ---------------------------------------------------------------------------
#define PITCH  72                         // halves per row (64 + 8 pad)
#define ST_A   (128 * PITCH * 2)          // 18432
#define ST_Bb  (64 * PITCH * 2)           // 9216 per branch
#define ST_TOT (ST_A + 2 * ST_Bb)         // 36864 per stage
#define EMB_SMEM (3 * ST_TOT)             // 110592

__global__ __launch_bounds__(256, 2)
void embed_hmma_kernel(const float* __restrict__ bhy, const float* __restrict__ bhg,
                       const float* __restrict__ bqy, const float* __restrict__ bqg)
{
    extern __shared__ __align__(16) char sm[];
    const uint32_t smu = smem_u32(sm);

    const int tid  = threadIdx.x;
    const int lane = tid & 31, wid = tid >> 5;
    const int wm = wid >> 1, wn = wid & 1;
    const int z  = blockIdx.z;
    const int m0 = blockIdx.x * 128;
    const int n0 = blockIdx.y * 64;

    const __half* Xf = &g_Xf[z][0][0];
    const __half* Wy = &g_Wf[2*z + 0][0][0];
    const __half* Wg = &g_Wf[2*z + 1][0][0];

    float acc[2][2][4][4];
    #pragma unroll
    for (int b = 0; b < 2; b++)
        #pragma unroll
        for (int mi = 0; mi < 2; mi++)
            #pragma unroll
            for (int ni = 0; ni < 4; ni++)
                #pragma unroll
                for (int r = 0; r < 4; r++) acc[b][mi][ni][r] = 0.f;

    // stage = 64 K. A: 128 rows x 8 segs; B: 2 branches x 64 rows x 8 segs.
    auto load_stage = [&](int s){
        const int k0 = s * 64, buf = s % 3;
        const uint32_t base = smu + buf * ST_TOT;
        #pragma unroll
        for (int i = 0; i < 4; i++){           // A: 1024 x 16B chunks
            int idx = tid + i * 256;
            int row = idx >> 3, seg = idx & 7;
            cpasync16(base + (row * PITCH + seg * 8) * 2,
                      Xf + (size_t)(m0 + row) * IN_ + k0 + seg * 8);
        }
        #pragma unroll
        for (int i = 0; i < 4; i++){           // B: 1024 x 16B chunks
            int idx = tid + i * 256;
            int t = idx >> 9, r = (idx >> 3) & 63, seg = idx & 7;
            const __half* W = t ? Wg : Wy;
            cpasync16(base + ST_A + t * ST_Bb + (r * PITCH + seg * 8) * 2,
                      W + (size_t)(n0 + r) * IN_ + k0 + seg * 8);
        }
    };

    load_stage(0); CP_COMMIT();
    load_stage(1); CP_COMMIT();

    const int lr = lane & 15;
    const int lc = (lane >> 4) * 8;

    for (int s = 0; s < 32; s++){
        if (s + 2 < 32) load_stage(s + 2);
        CP_COMMIT();                                  // uniform group cadence
        asm volatile("cp.async.wait_group 2;" ::: "memory");
        __syncthreads();

        const uint32_t base  = smu + (s % 3) * ST_TOT;
        const uint32_t bBase = base + ST_A;

        #pragma unroll
        for (int kk = 0; kk < 64; kk += 16){
            uint32_t a[2][4];
            #pragma unroll
            for (int mi = 0; mi < 2; mi++){
                uint32_t ad = base + ((wm*32 + mi*16 + lr) * PITCH + kk + lc) * 2;
                LDSM_X4(a[mi][0], a[mi][1], a[mi][2], a[mi][3], ad);
            }
            #pragma unroll
            for (int br = 0; br < 2; br++){
                uint32_t bb[4][2];
                #pragma unroll
                for (int hn = 0; hn < 2; hn++){
                    uint32_t t0, t1, t2, t3;
                    uint32_t bd = bBase + br * ST_Bb +
                                  ((wn*32 + hn*16 + lr) * PITCH + kk + lc) * 2;
                    LDSM_X4(t0, t1, t2, t3, bd);
                    bb[2*hn  ][0] = t0; bb[2*hn  ][1] = t2;
                    bb[2*hn+1][0] = t1; bb[2*hn+1][1] = t3;
                }
                #pragma unroll
                for (int mi = 0; mi < 2; mi++)
                    #pragma unroll
                    for (int ni = 0; ni < 4; ni++)
                        MMA16816(acc[br][mi][ni], a[mi], bb[ni]);
            }
        }
        __syncthreads();
    }

    const float* by = z ? bqy : bhy;
    const float* bg = z ? bqg : bhg;
    const int grp = lane >> 2, tig = lane & 3;
    #pragma unroll
    for (int mi = 0; mi < 2; mi++){
        #pragma unroll
        for (int ni = 0; ni < 4; ni++){
            const float* ay = acc[0][mi][ni];
            const float* ag = acc[1][mi][ni];
            const int gn  = n0 + wn*32 + ni*8 + tig*2;
            const int gm0 = m0 + wm*32 + mi*16 + grp;
            const float by0 = by[gn], by1 = by[gn+1];
            const float bg0 = bg[gn], bg1 = bg[gn+1];
            float2 o0, o1;
            {
                float g0 = ag[0] + bg0; g0 = g0 > 0.f ? g0 : 0.01f * g0;
                float g1 = ag[1] + bg1; g1 = g1 > 0.f ? g1 : 0.01f * g1;
                o0.x = tanhf(ay[0] + by0) * g0;
                o0.y = tanhf(ay[1] + by1) * g1;
            }
            {
                float g0 = ag[2] + bg0; g0 = g0 > 0.f ? g0 : 0.01f * g0;
                float g1 = ag[3] + bg1; g1 = g1 > 0.f ? g1 : 0.01f * g1;
                o1.x = tanhf(ay[2] + by0) * g0;
                o1.y = tanhf(ay[3] + by1) * g1;
            }
            *(float2*)&g_E[z][gm0    ][gn] = o0;
            *(float2*)&g_E[z][gm0 + 8][gn] = o1;
        }
    }
}

// ---------------------------------------------------------------------------
// score partial: grid (KSL, B_). Block computes 32x32 partial s/n over KCH k.
// ---------------------------------------------------------------------------
__global__ __launch_bounds__(256)
void score_part_kernel(const float* __restrict__ W_att)
{
    const int sl = blockIdx.x;
    const int b  = blockIdx.y;
    const int tid = threadIdx.x;
    const int kbase = sl * KCH;

    __shared__ float sq[64][33];
    __shared__ float sh[64][33];
    __shared__ __align__(16) float sw[64];

    const int q0 = tid >> 4;
    const int h0 = tid & 15;

    float s00 = 0.f, s01 = 0.f, s10 = 0.f, s11 = 0.f;
    float n00 = 0.f, n01 = 0.f, n10 = 0.f, n11 = 0.f;

    const float* Eq = &g_E[1][b * R_][0];
    const float* Eh = &g_E[0][b * R_][0];

    for (int k0 = kbase; k0 < kbase + KCH; k0 += 64) {
        #pragma unroll
        for (int i = 0; i < 2; i++) {
            int idx = tid + i * 256;
            int r   = idx >> 4;
            int c4  = (idx & 15) << 2;
            float4 vq = *(const float4*)(Eq + (size_t)r * H_ + k0 + c4);
            sq[c4 + 0][r] = vq.x; sq[c4 + 1][r] = vq.y;
            sq[c4 + 2][r] = vq.z; sq[c4 + 3][r] = vq.w;
            float4 vh = *(const float4*)(Eh + (size_t)r * H_ + k0 + c4);
            sh[c4 + 0][r] = vh.x; sh[c4 + 1][r] = vh.y;
            sh[c4 + 2][r] = vh.z; sh[c4 + 3][r] = vh.w;
        }
        if (tid < 16)
            *(float4*)&sw[tid << 2] = *(const float4*)(W_att + k0 + (tid << 2));
        __syncthreads();

        #pragma unroll 8
        for (int kk = 0; kk < 64; kk++) {
            float qa = sq[kk][q0], qb = sq[kk][q0 + 16];
            float ha = sh[kk][h0], hb = sh[kk][h0 + 16];
            float w  = sw[kk];
            float p;
            p = qa * ha; s00 += p * w; n00 += p * p;
            p = qa * hb; s01 += p * w; n01 += p * p;
            p = qb * ha; s10 += p * w; n10 += p * p;
            p = qb * hb; s11 += p * w; n11 += p * p;
        }
        __syncthreads();
    }

    g_spart[sl][b][q0     ][h0     ] = s00;
    g_spart[sl][b][q0     ][h0 + 16] = s01;
    g_spart[sl][b][q0 + 16][h0     ] = s10;
    g_spart[sl][b][q0 + 16][h0 + 16] = s11;
    g_npart[sl][b][q0     ][h0     ] = n00;
    g_npart[sl][b][q0     ][h0 + 16] = n01;
    g_npart[sl][b][q0 + 16][h0     ] = n10;
    g_npart[sl][b][q0 + 16][h0 + 16] = n11;
}

// ---------------------------------------------------------------------------
// score combine + masked softmax: grid B_, block 1024 (warp = q row, lane = h)
// ---------------------------------------------------------------------------
__global__ __launch_bounds__(1024)
void score_comb_kernel(const float* __restrict__ b_att_p)
{
    const int b = blockIdx.x;
    const int q = threadIdx.x >> 5;
    const int h = threadIdx.x & 31;

    float s = 0.f, n = 0.f;
    #pragma unroll
    for (int sl = 0; sl < KSL; sl++){
        s += g_spart[sl][b][q][h];
        n += g_npart[sl][b][q][h];
    }
    float x = s / fmaxf(sqrtf(n), 1e-12f) + b_att_p[0];

    bool valid = (h <= q);
    float xm = valid ? x : -1e30f;
    #pragma unroll
    for (int off = 16; off; off >>= 1)
        xm = fmaxf(xm, __shfl_xor_sync(0xffffffffu, xm, off));
    float e = valid ? expf(x - xm) : 0.f;
    float se = e;
    #pragma unroll
    for (int off = 16; off; off >>= 1)
        se += __shfl_xor_sync(0xffffffffu, se, off);
    g_att[b][q][h] = e / se;
}

// ---------------------------------------------------------------------------
// Kernel C: feat = att @ hist
// ---------------------------------------------------------------------------
__global__ __launch_bounds__(256)
void feat_kernel(const float* __restrict__ hist, float* __restrict__ out)
{
    const int b   = blockIdx.y;
    const int d0  = blockIdx.x * 256;
    const int tid = threadIdx.x;

    __shared__ __align__(16) float s_att[32][32];
    __shared__ __align__(16) float s_hist[32][256];

    ((float4*)s_att)[tid] = ((const float4*)&g_att[b][0][0])[tid];
    #pragma unroll
    for (int i = 0; i < 8; i++) {
        int idx = tid + i * 256;
        int h   = idx >> 6;
        int c4  = (idx & 63) << 2;
        *(float4*)&s_hist[h][c4] =
            *(const float4*)(hist + (size_t)(b * R_ + h) * IN_ + d0 + c4);
    }
    __syncthreads();

    float acc[32];
    #pragma unroll
    for (int q = 0; q < 32; q++) acc[q] = 0.f;
    #pragma unroll
    for (int h = 0; h < 32; h++) {
        float hv = s_hist[h][tid];
        #pragma unroll
        for (int q = 0; q < 32; q++)
            acc[q] += s_att[q][h] * hv;
    }
    #pragma unroll
    for (int q = 0; q < 32; q++)
        out[(size_t)(b * R_ + q) * IN_ + d0 + tid] = acc[q];
}

// ---------------------------------------------------------------------------
extern "C" void kernel_launch(void* const* d_in, const int* in_sizes, int n_in,
                              void* d_out, int out_size)
{
    const float* hist = (const float*)d_in[0];
    const float* ques = (const float*)d_in[1];
    const float* Why  = (const float*)d_in[2];
    const float* bhy  = (const float*)d_in[3];
    const float* Whg  = (const float*)d_in[4];
    const float* bhg  = (const float*)d_in[5];
    const float* Wqy  = (const float*)d_in[6];
    const float* bqy  = (const float*)d_in[7];
    const float* Wqg  = (const float*)d_in[8];
    const float* bqg  = (const float*)d_in[9];
    const float* Watt = (const float*)d_in[10];
    const float* batt = (const float*)d_in[11];
    float* out = (float*)d_out;

    cudaFuncSetAttribute(embed_hmma_kernel,
                         cudaFuncAttributeMaxDynamicSharedMemorySize, EMB_SMEM);

    convX_kernel<<<dim3(2048, 2), 256>>>(hist, ques);
    convW_kernel<<<dim3(32, 16, 4), 256>>>(Why, Whg, Wqy, Wqg);
    embed_hmma_kernel<<<dim3(16, 16, 2), 256, EMB_SMEM>>>(bhy, bhg, bqy, bqg);
    score_part_kernel<<<dim3(KSL, B_), 256>>>(Watt);
    score_comb_kernel<<<B_, 1024>>>(batt);
    feat_kernel<<<dim3(IN_ / 256, B_), 256>>>(hist, out);
}

// round 8
// speedup vs baseline: 4.8609x; 1.0971x over previous
#include <cuda_runtime.h>
#include <cuda_fp16.h>
#include <cstdint>
#include <math.h>

#define B_  64
#define R_  32
#define H_  1024
#define IN_ 2048
#define M_  (B_*R_)
#define KSL 8                 // score k-slices
#define KCH (H_/KSL)          // 128 k per slice

// ---------------- scratch (__device__ globals) -----------------------------
__device__ __align__(16) float  g_att[B_][R_][R_];         // softmax weights
__device__ __align__(16) __half g_Ehf[2][M_][H_];          // embeds fp16
__device__ __align__(16) __half g_Xf[2][M_][IN_];          // A fp16 [M,K]
__device__ __align__(16) __half g_Wf[4][H_][IN_];          // B fp16 [N,K] (W^T)
__device__ __align__(16) float  g_spart[KSL][B_][R_][R_];  // partial scores
__device__ __align__(16) float  g_npart[KSL][B_][R_][R_];  // partial norms

// ---------------- helpers --------------------------------------------------
__device__ __forceinline__ uint32_t smem_u32(const void* p){
    uint32_t a;
    asm("{ .reg .u64 t; cvta.to.shared.u64 t, %1; cvt.u32.u64 %0, t; }" : "=r"(a) : "l"(p));
    return a;
}
__device__ __forceinline__ void cpasync16(uint32_t dst, const void* src){
    asm volatile("cp.async.cg.shared.global [%0], [%1], 16;" :: "r"(dst), "l"(src));
}
#define CP_COMMIT() asm volatile("cp.async.commit_group;" ::: "memory")

#define LDSM_X4(d0,d1,d2,d3,addr) \
    asm volatile("ldmatrix.sync.aligned.m8n8.x4.shared.b16 {%0,%1,%2,%3}, [%4];" \
        : "=r"(d0),"=r"(d1),"=r"(d2),"=r"(d3) : "r"(addr))

#define MMA16816(c, a, b) \
    asm volatile("mma.sync.aligned.m16n8k16.row.col.f32.f16.f16.f32 " \
        "{%0,%1,%2,%3}, {%4,%5,%6,%7}, {%8,%9}, {%0,%1,%2,%3};" \
        : "+f"((c)[0]),"+f"((c)[1]),"+f"((c)[2]),"+f"((c)[3]) \
        : "r"((a)[0]),"r"((a)[1]),"r"((a)[2]),"r"((a)[3]), "r"((b)[0]),"r"((b)[1]))

__device__ __forceinline__ uint32_t sqr_h2(uint32_t x){
    __half2 h = *reinterpret_cast<__half2*>(&x);
    __half2 r = __hmul2(h, h);
    return *reinterpret_cast<uint32_t*>(&r);
}

// ---------------------------------------------------------------------------
// fused conv: part 1 (X fp32->fp16), part 2 (W transpose fp32->fp16 [N,K])
// grid 6144: [0,4096) convX, [4096,6144) convW
// ---------------------------------------------------------------------------
__global__ __launch_bounds__(256)
void conv_fused_kernel(const float* __restrict__ hist, const float* __restrict__ ques,
                       const float* __restrict__ W0, const float* __restrict__ W1,
                       const float* __restrict__ W2, const float* __restrict__ W3)
{
    const int bx = blockIdx.x;
    const int tid = threadIdx.x;
    if (bx < 4096){
        const int z = bx >> 11;
        const int xb = bx & 2047;
        const float* X = z ? ques : hist;
        __half* dst = &g_Xf[z][0][0];
        size_t i = ((size_t)xb * 256 + tid) * 8;
        float4 v0 = *(const float4*)(X + i);
        float4 v1 = *(const float4*)(X + i + 4);
        __half2 h[4];
        h[0] = __floats2half2_rn(v0.x, v0.y);
        h[1] = __floats2half2_rn(v0.z, v0.w);
        h[2] = __floats2half2_rn(v1.x, v1.y);
        h[3] = __floats2half2_rn(v1.z, v1.w);
        *(uint4*)(dst + i) = *(uint4*)h;
    } else {
        const float* Ws[4] = {W0, W1, W2, W3};
        const int wb  = bx - 4096;          // [0, 2048)
        const int br  = wb >> 9;            // branch
        const int rem = wb & 511;
        const int n0  = (rem >> 5) * 64;    // 16 n blocks
        const int k0  = (rem & 31) * 64;    // 32 k blocks
        const float* W = Ws[br];
        __shared__ float s[64][65];
        #pragma unroll
        for (int i = 0; i < 4; i++){
            int idx = tid + i * 256;
            int r = idx >> 4;
            int c = (idx & 15) * 4;
            float4 v = *(const float4*)(W + (size_t)(k0 + r) * H_ + n0 + c);
            s[r][c] = v.x; s[r][c+1] = v.y; s[r][c+2] = v.z; s[r][c+3] = v.w;
        }
        __syncthreads();
        int nl  = tid >> 2;
        int seg = (tid & 3) * 16;
        __half2 h[8];
        #pragma unroll
        for (int j = 0; j < 8; j++)
            h[j] = __floats2half2_rn(s[seg + 2*j][nl], s[seg + 2*j + 1][nl]);
        __half* o = &g_Wf[br][n0 + nl][k0 + seg];
        *(uint4*)(o)     = *(uint4*)&h[0];
        *(uint4*)(o + 8) = *(uint4*)&h[4];
    }
}

// ---------------------------------------------------------------------------
// embed GEMM: HMMA m16n8k16 fp16, fused dual-branch, 3-stage cp.async, BK=64.
// Epilogue: bias + tanh*leaky_relu -> g_Ehf (fp16).
// ---------------------------------------------------------------------------
#define PITCH  72
#define ST_A   (128 * PITCH * 2)
#define ST_Bb  (64 * PITCH * 2)
#define ST_TOT (ST_A + 2 * ST_Bb)
#define EMB_SMEM (3 * ST_TOT)

__global__ __launch_bounds__(256, 2)
void embed_hmma_kernel(const float* __restrict__ bhy, const float* __restrict__ bhg,
                       const float* __restrict__ bqy, const float* __restrict__ bqg)
{
    extern __shared__ __align__(16) char sm[];
    const uint32_t smu = smem_u32(sm);

    const int tid  = threadIdx.x;
    const int lane = tid & 31, wid = tid >> 5;
    const int wm = wid >> 1, wn = wid & 1;
    const int z  = blockIdx.z;
    const int m0 = blockIdx.x * 128;
    const int n0 = blockIdx.y * 64;

    const __half* Xf = &g_Xf[z][0][0];
    const __half* Wy = &g_Wf[2*z + 0][0][0];
    const __half* Wg = &g_Wf[2*z + 1][0][0];

    float acc[2][2][4][4];
    #pragma unroll
    for (int b = 0; b < 2; b++)
        #pragma unroll
        for (int mi = 0; mi < 2; mi++)
            #pragma unroll
            for (int ni = 0; ni < 4; ni++)
                #pragma unroll
                for (int r = 0; r < 4; r++) acc[b][mi][ni][r] = 0.f;

    auto load_stage = [&](int s){
        const int k0 = s * 64, buf = s % 3;
        const uint32_t base = smu + buf * ST_TOT;
        #pragma unroll
        for (int i = 0; i < 4; i++){
            int idx = tid + i * 256;
            int row = idx >> 3, seg = idx & 7;
            cpasync16(base + (row * PITCH + seg * 8) * 2,
                      Xf + (size_t)(m0 + row) * IN_ + k0 + seg * 8);
        }
        #pragma unroll
        for (int i = 0; i < 4; i++){
            int idx = tid + i * 256;
            int t = idx >> 9, r = (idx >> 3) & 63, seg = idx & 7;
            const __half* W = t ? Wg : Wy;
            cpasync16(base + ST_A + t * ST_Bb + (r * PITCH + seg * 8) * 2,
                      W + (size_t)(n0 + r) * IN_ + k0 + seg * 8);
        }
    };

    load_stage(0); CP_COMMIT();
    load_stage(1); CP_COMMIT();

    const int lr = lane & 15;
    const int lc = (lane >> 4) * 8;

    for (int s = 0; s < 32; s++){
        if (s + 2 < 32) load_stage(s + 2);
        CP_COMMIT();
        asm volatile("cp.async.wait_group 2;" ::: "memory");
        __syncthreads();

        const uint32_t base  = smu + (s % 3) * ST_TOT;
        const uint32_t bBase = base + ST_A;

        #pragma unroll
        for (int kk = 0; kk < 64; kk += 16){
            uint32_t a[2][4];
            #pragma unroll
            for (int mi = 0; mi < 2; mi++){
                uint32_t ad = base + ((wm*32 + mi*16 + lr) * PITCH + kk + lc) * 2;
                LDSM_X4(a[mi][0], a[mi][1], a[mi][2], a[mi][3], ad);
            }
            #pragma unroll
            for (int br = 0; br < 2; br++){
                uint32_t bb[4][2];
                #pragma unroll
                for (int hn = 0; hn < 2; hn++){
                    uint32_t t0, t1, t2, t3;
                    uint32_t bd = bBase + br * ST_Bb +
                                  ((wn*32 + hn*16 + lr) * PITCH + kk + lc) * 2;
                    LDSM_X4(t0, t1, t2, t3, bd);
                    bb[2*hn  ][0] = t0; bb[2*hn  ][1] = t2;
                    bb[2*hn+1][0] = t1; bb[2*hn+1][1] = t3;
                }
                #pragma unroll
                for (int mi = 0; mi < 2; mi++)
                    #pragma unroll
                    for (int ni = 0; ni < 4; ni++)
                        MMA16816(acc[br][mi][ni], a[mi], bb[ni]);
            }
        }
        __syncthreads();
    }

    const float* by = z ? bqy : bhy;
    const float* bg = z ? bqg : bhg;
    const int grp = lane >> 2, tig = lane & 3;
    #pragma unroll
    for (int mi = 0; mi < 2; mi++){
        #pragma unroll
        for (int ni = 0; ni < 4; ni++){
            const float* ay = acc[0][mi][ni];
            const float* ag = acc[1][mi][ni];
            const int gn  = n0 + wn*32 + ni*8 + tig*2;
            const int gm0 = m0 + wm*32 + mi*16 + grp;
            const float by0 = by[gn], by1 = by[gn+1];
            const float bg0 = bg[gn], bg1 = bg[gn+1];
            float g0 = ag[0] + bg0; g0 = g0 > 0.f ? g0 : 0.01f * g0;
            float g1 = ag[1] + bg1; g1 = g1 > 0.f ? g1 : 0.01f * g1;
            float g2 = ag[2] + bg0; g2 = g2 > 0.f ? g2 : 0.01f * g2;
            float g3 = ag[3] + bg1; g3 = g3 > 0.f ? g3 : 0.01f * g3;
            __half2 o0 = __floats2half2_rn(tanhf(ay[0] + by0) * g0,
                                           tanhf(ay[1] + by1) * g1);
            __half2 o1 = __floats2half2_rn(tanhf(ay[2] + by0) * g2,
                                           tanhf(ay[3] + by1) * g3);
            *(__half2*)&g_Ehf[z][gm0    ][gn] = o0;
            *(__half2*)&g_Ehf[z][gm0 + 8][gn] = o1;
        }
    }
}

// ---------------------------------------------------------------------------
// score via HMMA: S = Eq @ (Eh.w)^T, N = Eq^2 @ (Eh^2)^T, split-K (KSL, B_).
// 128 thr = 4 warps, warp (wm, wn) computes m16 x n16 of both 32x32 outputs.
// Squared fragments via elementwise __hmul2 on ldmatrix fragments.
// Smem fill: 512 uint4 chunks per buffer (32 rows x 16 segs) — 4 iters x 128.
// ---------------------------------------------------------------------------
#define SPITCH 136

__global__ __launch_bounds__(128)
void score_hmma_kernel(const float* __restrict__ W_att)
{
    __shared__ __align__(16) __half sq [32 * SPITCH];
    __shared__ __align__(16) __half shh[32 * SPITCH];
    __shared__ __align__(16) __half shw[32 * SPITCH];

    const int sl = blockIdx.x;
    const int b  = blockIdx.y;
    const int kb = sl * KCH;
    const int tid = threadIdx.x, lane = tid & 31, w = tid >> 5;

    #pragma unroll
    for (int i = 0; i < 4; i++){
        int idx = tid + i * 128;          // 0..511
        int r   = idx >> 4;               // 0..31
        int seg = idx & 15;               // 0..15 (8 halves each -> 128 k)
        uint4 vq = *(const uint4*)&g_Ehf[1][b*R_ + r][kb + seg*8];
        *(uint4*)&sq[r * SPITCH + seg*8] = vq;
        uint4 vh = *(const uint4*)&g_Ehf[0][b*R_ + r][kb + seg*8];
        *(uint4*)&shh[r * SPITCH + seg*8] = vh;
        const float* wp = W_att + kb + seg*8;
        float4 w0 = *(const float4*)wp;
        float4 w1 = *(const float4*)(wp + 4);
        const __half* h8 = (const __half*)&vh;
        __half o8[8];
        o8[0] = __float2half_rn(__half2float(h8[0]) * w0.x);
        o8[1] = __float2half_rn(__half2float(h8[1]) * w0.y);
        o8[2] = __float2half_rn(__half2float(h8[2]) * w0.z);
        o8[3] = __float2half_rn(__half2float(h8[3]) * w0.w);
        o8[4] = __float2half_rn(__half2float(h8[4]) * w1.x);
        o8[5] = __float2half_rn(__half2float(h8[5]) * w1.y);
        o8[6] = __float2half_rn(__half2float(h8[6]) * w1.z);
        o8[7] = __float2half_rn(__half2float(h8[7]) * w1.w);
        *(uint4*)&shw[r * SPITCH + seg*8] = *(uint4*)o8;
    }
    __syncthreads();

    const int wm = w & 1, wn = w >> 1;
    const int lr = lane & 15, lc = (lane >> 4) * 8;
    const uint32_t aB = smem_u32(sq);
    const uint32_t hB = smem_u32(shh);
    const uint32_t wB = smem_u32(shw);

    float cs[2][4] = {{0,0,0,0},{0,0,0,0}};
    float cn[2][4] = {{0,0,0,0},{0,0,0,0}};

    #pragma unroll
    for (int kk = 0; kk < KCH; kk += 16){
        uint32_t a[4], a2[4];
        LDSM_X4(a[0], a[1], a[2], a[3], aB + ((wm*16 + lr) * SPITCH + kk + lc) * 2);
        #pragma unroll
        for (int i = 0; i < 4; i++) a2[i] = sqr_h2(a[i]);

        uint32_t tw0, tw1, tw2, tw3;
        LDSM_X4(tw0, tw1, tw2, tw3, wB + ((wn*16 + lr) * SPITCH + kk + lc) * 2);
        uint32_t th0, th1, th2, th3;
        LDSM_X4(th0, th1, th2, th3, hB + ((wn*16 + lr) * SPITCH + kk + lc) * 2);

        uint32_t bS0[2] = {tw0, tw2}, bS1[2] = {tw1, tw3};
        uint32_t b20[2] = {sqr_h2(th0), sqr_h2(th2)};
        uint32_t b21[2] = {sqr_h2(th1), sqr_h2(th3)};

        MMA16816(cs[0], a, bS0);
        MMA16816(cs[1], a, bS1);
        MMA16816(cn[0], a2, b20);
        MMA16816(cn[1], a2, b21);
    }

    const int grp = lane >> 2, tig = lane & 3;
    const int q0 = wm * 16 + grp;
    #pragma unroll
    for (int t = 0; t < 2; t++){
        const int hc = wn * 16 + t * 8 + tig * 2;
        *(float2*)&g_spart[sl][b][q0    ][hc] = make_float2(cs[t][0], cs[t][1]);
        *(float2*)&g_spart[sl][b][q0 + 8][hc] = make_float2(cs[t][2], cs[t][3]);
        *(float2*)&g_npart[sl][b][q0    ][hc] = make_float2(cn[t][0], cn[t][1]);
        *(float2*)&g_npart[sl][b][q0 + 8][hc] = make_float2(cn[t][2], cn[t][3]);
    }
}

// ---------------------------------------------------------------------------
// score combine + masked softmax: grid B_, block 1024 (warp = q row, lane = h)
// ---------------------------------------------------------------------------
__global__ __launch_bounds__(1024)
void score_comb_kernel(const float* __restrict__ b_att_p)
{
    const int b = blockIdx.x;
    const int q = threadIdx.x >> 5;
    const int h = threadIdx.x & 31;

    float s = 0.f, n = 0.f;
    #pragma unroll
    for (int sl = 0; sl < KSL; sl++){
        s += g_spart[sl][b][q][h];
        n += g_npart[sl][b][q][h];
    }
    float x = s / fmaxf(sqrtf(n), 1e-12f) + b_att_p[0];

    bool valid = (h <= q);
    float xm = valid ? x : -1e30f;
    #pragma unroll
    for (int off = 16; off; off >>= 1)
        xm = fmaxf(xm, __shfl_xor_sync(0xffffffffu, xm, off));
    float e = valid ? expf(x - xm) : 0.f;
    float se = e;
    #pragma unroll
    for (int off = 16; off; off >>= 1)
        se += __shfl_xor_sync(0xffffffffu, se, off);
    g_att[b][q][h] = e / se;
}

// ---------------------------------------------------------------------------
// feat = att @ hist: 2 d-columns per thread (amortize att broadcast LDS).
// grid (IN_/512, B_), 256 thr, dyn smem: att 4KB + hist 32x512 fp32 64KB.
// ---------------------------------------------------------------------------
#define FEAT_SMEM ((1024 + 32 * 512) * 4)

__global__ __launch_bounds__(256)
void feat_kernel(const float* __restrict__ hist, float* __restrict__ out)
{
    extern __shared__ __align__(16) float fsm[];
    float* s_att  = fsm;              // [32][32]
    float* s_hist = fsm + 1024;       // [32][512]

    const int b   = blockIdx.y;
    const int d0  = blockIdx.x * 512;
    const int tid = threadIdx.x;

    ((float4*)s_att)[tid] = ((const float4*)&g_att[b][0][0])[tid];
    #pragma unroll
    for (int i = 0; i < 16; i++){
        int idx = tid + i * 256;          // 0..4095 float4 units
        int h   = idx >> 7;               // 0..31
        int c4  = (idx & 127) << 2;       // 0..508
        *(float4*)&s_hist[h * 512 + c4] =
            *(const float4*)(hist + (size_t)(b * R_ + h) * IN_ + d0 + c4);
    }
    __syncthreads();

    float acc0[32], acc1[32];
    #pragma unroll
    for (int q = 0; q < 32; q++){ acc0[q] = 0.f; acc1[q] = 0.f; }
    #pragma unroll
    for (int h = 0; h < 32; h++){
        float hv0 = s_hist[h * 512 + tid];
        float hv1 = s_hist[h * 512 + tid + 256];
        #pragma unroll
        for (int q = 0; q < 32; q++){
            float av = s_att[q * 32 + h];
            acc0[q] += av * hv0;
            acc1[q] += av * hv1;
        }
    }
    #pragma unroll
    for (int q = 0; q < 32; q++){
        out[(size_t)(b * R_ + q) * IN_ + d0 + tid]       = acc0[q];
        out[(size_t)(b * R_ + q) * IN_ + d0 + tid + 256] = acc1[q];
    }
}

// ---------------------------------------------------------------------------
extern "C" void kernel_launch(void* const* d_in, const int* in_sizes, int n_in,
                              void* d_out, int out_size)
{
    const float* hist = (const float*)d_in[0];
    const float* ques = (const float*)d_in[1];
    const float* Why  = (const float*)d_in[2];
    const float* bhy  = (const float*)d_in[3];
    const float* Whg  = (const float*)d_in[4];
    const float* bhg  = (const float*)d_in[5];
    const float* Wqy  = (const float*)d_in[6];
    const float* bqy  = (const float*)d_in[7];
    const float* Wqg  = (const float*)d_in[8];
    const float* bqg  = (const float*)d_in[9];
    const float* Watt = (const float*)d_in[10];
    const float* batt = (const float*)d_in[11];
    float* out = (float*)d_out;

    cudaFuncSetAttribute(embed_hmma_kernel,
                         cudaFuncAttributeMaxDynamicSharedMemorySize, EMB_SMEM);
    cudaFuncSetAttribute(feat_kernel,
                         cudaFuncAttributeMaxDynamicSharedMemorySize, FEAT_SMEM);

    conv_fused_kernel<<<6144, 256>>>(hist, ques, Why, Whg, Wqy, Wqg);
    embed_hmma_kernel<<<dim3(16, 16, 2), 256, EMB_SMEM>>>(bhy, bhg, bqy, bqg);
    score_hmma_kernel<<<dim3(KSL, B_), 128>>>(Watt);
    score_comb_kernel<<<B_, 1024>>>(batt);
    feat_kernel<<<dim3(IN_ / 512, B_), 256, FEAT_SMEM>>>(hist, out);
}